// round 6
// baseline (speedup 1.0000x reference)
#include <cuda_runtime.h>
#include <cstdint>

#define TT 256
#define HH 512
#define VV 32
#define NBATCH 16

typedef unsigned long long u64;

// ---------------- device scratch (static, no allocation) ----------------
__device__ float g_Kproj[NBATCH*TT*HH];     // 8 MB
__device__ float g_q[NBATCH*HH];
__device__ float g_scores[NBATCH*TT];
__device__ float g_ctx[NBATCH*HH];
__device__ float g_h0[2][NBATCH*HH];
__device__ float g_c0[2][NBATCH*HH];        // used by fallback only
__device__ float g_h1[2][NBATCH*HH];
__device__ float g_c1[2][NBATCH*HH];        // used by fallback only

// barrier state: monotonic across launches (graph replays) -> no reset race
__device__ unsigned g_epoch;
__device__ unsigned g_arrive;
__device__ unsigned g_release;

// ---------------- helpers ----------------
union F4 { float4 v; u64 u[2]; };
union F2 { u64 u; float2 f; };

__device__ __forceinline__ void fma2(u64 &acc, u64 a, u64 b){
    asm("fma.rn.f32x2 %0, %1, %2, %0;" : "+l"(acc) : "l"(a), "l"(b));
}
__device__ __forceinline__ float wsum(float v){
#pragma unroll
    for (int o = 16; o; o >>= 1) v += __shfl_xor_sync(0xffffffffu, v, o);
    return v;
}
__device__ __forceinline__ u64 wsum2(u64 v){
#pragma unroll
    for (int o = 16; o; o >>= 1){
        u64 other = __shfl_xor_sync(0xffffffffu, v, o);
        asm("add.rn.f32x2 %0, %0, %1;" : "+l"(v) : "l"(other));
    }
    return v;
}
__device__ __forceinline__ float wmax(float v){
#pragma unroll
    for (int o = 16; o; o >>= 1) v = fmaxf(v, __shfl_xor_sync(0xffffffffu, v, o));
    return v;
}
__device__ __forceinline__ float sigf(float x){ return 1.0f/(1.0f + __expf(-x)); }

// MUFU-free tanh, |err| ~1e-5
__device__ __forceinline__ float tanh_fast(float x){
    float u = x * 2.8853900817779268f;
    u = fminf(fmaxf(u, -30.0f), 30.0f);
    float big = u + 12582912.0f;
    int e = __float_as_int(big) - 0x4B400000;
    float fn = big - 12582912.0f;
    float f = u - fn;
    float p = 1.3333558e-3f;
    p = fmaf(p, f, 9.6181291e-3f);
    p = fmaf(p, f, 5.5504109e-2f);
    p = fmaf(p, f, 2.4022651e-1f);
    p = fmaf(p, f, 6.9314718e-1f);
    p = fmaf(p, f, 1.0f);
    float t = __int_as_float(__float_as_int(p) + (e << 23));
    float num = t - 1.0f;
    float den = t + 1.0f;
    float r = __uint_as_float(0x7EF311C3u - __float_as_uint(den));
    r = r * fmaf(-den, r, 2.0f);
    r = r * fmaf(-den, r, 2.0f);
    return num * r;
}

// grid barrier: atomic arrive + single release flag
__device__ __forceinline__ void gridbar(unsigned &ep, int NB){
    __syncthreads();
    ep++;
    if (threadIdx.x == 0){
        __threadfence();
        unsigned prev = atomicAdd(&g_arrive, 1u);
        if (prev + 1u == ep * (unsigned)NB){
            __threadfence();
            *(volatile unsigned*)&g_release = ep;
        } else {
            while (*(volatile unsigned*)&g_release < ep) __nanosleep(20);
        }
        __threadfence();
    }
    __syncthreads();
}

// ---------------- batch-shared GEMV row (fallback path) ----------
__device__ __forceinline__ void dotrow16(const float* __restrict__ Wrow,
                                         const float4* __restrict__ hs4,
                                         float bias, float* dst, int dstStride, int lane){
    u64 acc2[16];
#pragma unroll
    for (int b=0;b<16;b++) acc2[b]=0ull;
    const float4* W4 = (const float4*)Wrow;
    F4 Wv[4];
#pragma unroll
    for (int i=0;i<4;i++) Wv[i].v = __ldcg(W4 + lane + 32*i);
#pragma unroll
    for (int i=0;i<4;i++){
#pragma unroll
        for (int b=0;b<16;b++){
            F4 X; X.v = hs4[b*128 + lane + 32*i];
            fma2(acc2[b], Wv[i].u[0], X.u[0]);
            fma2(acc2[b], Wv[i].u[1], X.u[1]);
        }
    }
#pragma unroll
    for (int b=0;b<16;b++){
        F2 z; z.u = acc2[b];
        float s = z.f.x + z.f.y;
        s = wsum(s);
        if (lane==b) dst[(size_t)b*dstStride] = s + bias;
    }
}

// ---------------- Kproj = enc @ Wk^T + bk (one-time tiled GEMM) ----------------
__device__ void kproj_phase(const float* __restrict__ A, const float* __restrict__ W,
                            const float* __restrict__ bias, float* __restrict__ C,
                            float* sm, int NB, int bx, int tid){
    float* As = sm;
    float* Ws = sm + 16*65;
    int lr = tid >> 2;
    int lk = (tid & 3) << 2;
    int tx = tid & 15, ty = tid >> 4;
    for (int tile = bx; tile < 64*8; tile += NB){
        int m0 = (tile >> 3)*64, n0 = (tile & 7)*64;
        float acc[4][4];
#pragma unroll
        for (int i=0;i<4;i++)
#pragma unroll
            for (int j=0;j<4;j++) acc[i][j]=0.f;
        for (int k0 = 0; k0 < HH; k0 += 16){
            float4 a4 = *(const float4*)(A + (size_t)(m0+lr)*HH + k0 + lk);
            float4 w4 = *(const float4*)(W + (size_t)(n0+lr)*HH + k0 + lk);
            __syncthreads();
            As[(lk+0)*65+lr]=a4.x; As[(lk+1)*65+lr]=a4.y; As[(lk+2)*65+lr]=a4.z; As[(lk+3)*65+lr]=a4.w;
            Ws[(lk+0)*65+lr]=w4.x; Ws[(lk+1)*65+lr]=w4.y; Ws[(lk+2)*65+lr]=w4.z; Ws[(lk+3)*65+lr]=w4.w;
            __syncthreads();
#pragma unroll
            for (int kk=0; kk<16; kk++){
                float av[4], wv[4];
#pragma unroll
                for (int i=0;i<4;i++){ av[i]=As[kk*65 + ty*4+i]; wv[i]=Ws[kk*65 + tx*4+i]; }
#pragma unroll
                for (int i=0;i<4;i++)
#pragma unroll
                    for (int j=0;j<4;j++) acc[i][j] += av[i]*wv[j];
            }
        }
#pragma unroll
        for (int i=0;i<4;i++){
            int m = m0 + ty*4 + i;
#pragma unroll
            for (int j=0;j<4;j++){
                int n = n0 + tx*4 + j;
                C[(size_t)m*HH + n] = acc[i][j] + bias[n];
            }
        }
        __syncthreads();
    }
}

// =====================================================================
// MAIN: register/smem-resident-weight persistent kernel (requires grid==148)
// =====================================================================
// smem layout (floats):
//   [0,16384)        wl1: layer1 weights [8 warps][2 gates][1024 k]
//   [16384,16400)    bsum0[4 cells][4 gates]
//   [16400,16416)    bsum1
//   [16416,16480)    c0s[4][16]
//   [16480,16544)    c1s[4][16]
//   [16544,16800)    gsc[4 cells][4 gates][16 b]
//   [16800, ...)     transient (xsT rows stride 18 for D/E; staging for A/B/C; kproj)
#define PERSIST 16800
#define XSTRIDE 18
#define SMEM_REG ((PERSIST + 1536*XSTRIDE) * 4)   // 177792 bytes

// transpose-stage one b-major [16][512] source into xsT rows [kbase..kbase+512)
__device__ __forceinline__ void stageT(float* tb, int kbase, const float4* __restrict__ src4,
                                       int srcStride4 /*float4 per b row*/, int tid){
#pragma unroll
    for (int r = 0; r < 8; r++){
        int f4 = tid + 256*r;            // 0..2047
        int b = f4 >> 7;                 // 128 float4 per batch
        int k4 = f4 & 127;
        float4 vv = __ldcg(src4 + (size_t)b*srcStride4 + k4);
        float* d = tb + (size_t)(kbase + 4*k4)*XSTRIDE + b;
        d[0*XSTRIDE] = vv.x; d[1*XSTRIDE] = vv.y; d[2*XSTRIDE] = vv.z; d[3*XSTRIDE] = vv.w;
    }
}

__global__ __launch_bounds__(256, 1)
void decoder_reg(const float* __restrict__ enc, const float* __restrict__ h0in,
                 const float* __restrict__ c0in,
                 const float* __restrict__ Wq, const float* __restrict__ bq,
                 const float* __restrict__ Wk, const float* __restrict__ bk,
                 const float* __restrict__ v,
                 const float* __restrict__ Wih0, const float* __restrict__ bih0,
                 const float* __restrict__ Whh0, const float* __restrict__ bhh0,
                 const float* __restrict__ Wih1, const float* __restrict__ bih1,
                 const float* __restrict__ Whh1, const float* __restrict__ bhh1,
                 const float* __restrict__ Wout, const float* __restrict__ bout,
                 float* __restrict__ out)
{
    extern __shared__ float sm[];
    float* tb = sm + PERSIST;
    const int tid = threadIdx.x, bx = blockIdx.x, NB = gridDim.x;   // NB == 148
    const int lane = tid & 31, w = tid >> 5;
    const int NW = NB * 8;
    const bool lstmBlk = (bx < 128);
    const int cl = w >> 1;                  // local cell 0..3
    const int gp = w & 1;                   // gate pair: 0->(i,f) 1->(g,o)
    const int cell = bx*4 + cl;             // global cell (lstm blocks)
    unsigned ep = g_epoch;

    // ---------------- persistent weights ----------------
    float wl0[2][48];                       // layer0: 2 gates x (32 ih + 16 hh) per lane
    u64   wqr[4][8];                        // A-blocks: 4 rows of Wq/Wout as k-pairs
    float wbr[4];
    int   wr = 0;

    if (lstmBlk){
#pragma unroll
        for (int g2 = 0; g2 < 2; g2++){
            int row = cell + 512*(gp*2 + g2);
#pragma unroll
            for (int j = 0; j < 32; j++)
                wl0[g2][j] = Wih0[(size_t)row*1024 + lane + 32*j];
#pragma unroll
            for (int j = 0; j < 16; j++)
                wl0[g2][32+j] = Whh0[(size_t)row*512 + lane + 32*j];
        }
        // layer1 weights -> smem (once): wl1[w][g2][k], k: [0,512)=ih, [512,1024)=hh
#pragma unroll
        for (int g2 = 0; g2 < 2; g2++){
            int row = cell + 512*(gp*2 + g2);
            float* dst = sm + ((w*2 + g2)*1024);
            for (int j = 0; j < 16; j++) dst[lane + 32*j]       = Wih1[(size_t)row*512 + lane + 32*j];
            for (int j = 0; j < 16; j++) dst[512 + lane + 32*j] = Whh1[(size_t)row*512 + lane + 32*j];
        }
        // biases + c-state
        if (tid < 16){
            int cc = bx*4 + (tid >> 2), g = tid & 3;
            sm[16384 + tid] = bih0[cc + 512*g] + bhh0[cc + 512*g];
            sm[16400 + tid] = bih1[cc + 512*g] + bhh1[cc + 512*g];
        }
        if (tid < 64){
            int ccl = tid >> 4, b = tid & 15;
            sm[16416 + ccl*16 + b] = c0in[(size_t)b*512 + bx*4 + ccl];
            sm[16480 + ccl*16 + b] = c0in[8192 + (size_t)b*512 + bx*4 + ccl];
        }
    } else {
        wr = (bx - 128)*8 + w;              // 0..159
#pragma unroll
        for (int jj = 0; jj < 4; jj++){
            int row = wr + 160*jj;
            const float* src = nullptr; float bb = 0.f;
            if (row < 512){ src = Wq + (size_t)row*512; bb = bq[row]; }
            else if (row < 544){ src = Wout + (size_t)(row-512)*512; bb = bout[row-512]; }
            wbr[jj] = bb;
#pragma unroll
            for (int i = 0; i < 4; i++){
                F4 t4; 
                if (src) t4.v = *(const float4*)(src + 4*(lane + 32*i));
                else { t4.v = make_float4(0.f,0.f,0.f,0.f); }
                wqr[jj][2*i]   = t4.u[0];
                wqr[jj][2*i+1] = t4.u[1];
            }
        }
    }

    // ---------------- init state + Kproj ----------------
    for (int i = bx*256 + tid; i < NBATCH*HH; i += NB*256){
        g_h0[0][i] = h0in[i];
        g_h1[0][i] = h0in[NBATCH*HH + i];
    }
    __syncthreads();
    kproj_phase(enc, Wk, bk, g_Kproj, tb, NB, bx, tid);
    gridbar(ep, NB);

    for (int t = 0; t < TT; t++){
        const int p = t & 1, np = p ^ 1;

        // ---- phase A: q + logits[t-1] (blocks 128..147 only) ----
        if (!lstmBlk){
            float4* hs4 = (float4*)tb;
            const float4* hsrc = (const float4*)g_h1[p];
            for (int i = tid; i < 2048; i += 256) hs4[i] = __ldcg(hsrc + i);
            __syncthreads();
#pragma unroll
            for (int jj = 0; jj < 4; jj++){
                int row = wr + 160*jj;
                if (row >= 544) continue;
                if (row >= 512 && t == 0) continue;
                u64 acc2[16];
#pragma unroll
                for (int b=0;b<16;b++) acc2[b]=0ull;
#pragma unroll
                for (int i = 0; i < 4; i++){
#pragma unroll
                    for (int b = 0; b < 16; b++){
                        F4 X; X.v = hs4[b*128 + lane + 32*i];
                        fma2(acc2[b], wqr[jj][2*i],   X.u[0]);
                        fma2(acc2[b], wqr[jj][2*i+1], X.u[1]);
                    }
                }
#pragma unroll
                for (int b = 0; b < 16; b++){
                    F2 z; z.u = acc2[b];
                    float s = wsum(z.f.x + z.f.y);
                    if (lane == b){
                        if (row < 512) g_q[b*HH + row] = s + wbr[jj];
                        else out[((size_t)b*TT + (t-1))*VV + (row-512)] = s + wbr[jj];
                    }
                }
            }
        }
        gridbar(ep, NB);

        // ---- phase B: scores (all blocks; warp handles a tau-pair) ----
        {
            float4* qs4 = (float4*)tb;
            float*  vs  = tb + NBATCH*HH;
            const float4* qsrc = (const float4*)g_q;
            for (int i = tid; i < 2048; i += 256) qs4[i] = __ldcg(qsrc + i);
            for (int i = tid; i < HH;  i += 256) vs[i] = v[i];
            __syncthreads();
            const float4* vs4 = (const float4*)vs;
            for (int pr = w*NB + bx; pr < 2048; pr += NW){
                int b = pr >> 7;
                const float4* Ka = (const float4*)(g_Kproj + ((size_t)pr*2)*HH);
                const float4* Kb = Ka + 128;
                float4 ka[4], kb[4];
#pragma unroll
                for (int i = 0; i < 4; i++){
                    ka[i] = __ldcg(Ka + lane + 32*i);
                    kb[i] = __ldcg(Kb + lane + 32*i);
                }
                float a0 = 0.f, a1 = 0.f;
#pragma unroll
                for (int i = 0; i < 4; i++){
                    int c = lane + 32*i;
                    float4 q4 = qs4[b*128 + c];
                    float4 v4 = vs4[c];
                    a0 += v4.x * tanh_fast(q4.x + ka[i].x);
                    a0 += v4.y * tanh_fast(q4.y + ka[i].y);
                    a0 += v4.z * tanh_fast(q4.z + ka[i].z);
                    a0 += v4.w * tanh_fast(q4.w + ka[i].w);
                    a1 += v4.x * tanh_fast(q4.x + kb[i].x);
                    a1 += v4.y * tanh_fast(q4.y + kb[i].y);
                    a1 += v4.z * tanh_fast(q4.z + kb[i].z);
                    a1 += v4.w * tanh_fast(q4.w + kb[i].w);
                }
                a0 = wsum(a0); a1 = wsum(a1);
                if (lane == 0){ g_scores[2*pr] = a0; g_scores[2*pr+1] = a1; }
            }
        }
        gridbar(ep, NB);

        // ---- phase C: softmax + ctx (blocks 0..127) ----
        if (bx < 128){
            float* ws  = tb;
            float* red = tb + 256;
            float* sP  = tb + 272;
            int b = bx >> 3, hc = (bx & 7) * 64;
            float s = g_scores[b*TT + tid];
            float m = wmax(s);
            if (lane == 0) red[w] = m;
            __syncthreads();
            float mx = red[0];
#pragma unroll
            for (int j = 1; j < 8; j++) mx = fmaxf(mx, red[j]);
            float e = __expf(s - mx);
            ws[tid] = e;
            float su = wsum(e);
            if (lane == 0) red[w] = su;
            __syncthreads();
            float tot = red[0];
#pragma unroll
            for (int j = 1; j < 8; j++) tot += red[j];
            float rz = 1.f / tot;
            int h = hc + (tid & 63), stripe = tid >> 6;
            const float* ep_ = enc + ((size_t)(b*TT) + stripe*64)*HH + h;
            float acc = 0.f;
#pragma unroll 8
            for (int tt2 = 0; tt2 < 64; tt2++) acc += ws[stripe*64 + tt2] * __ldcg(ep_ + (size_t)tt2*HH);
            sP[tid] = acc; __syncthreads();
            if (tid < 64)
                g_ctx[b*HH + hc + tid] = (sP[tid] + sP[tid+64] + sP[tid+128] + sP[tid+192]) * rz;
        }
        gridbar(ep, NB);

        // ---- phase D: LSTM layer0 from register weights ----
        if (lstmBlk){
            stageT(tb,    0, (const float4*)enc + (size_t)t*128, TT*128, tid);  // enc[b][t][:]
            stageT(tb,  512, (const float4*)g_ctx,   128, tid);
            stageT(tb, 1024, (const float4*)g_h0[p], 128, tid);
            __syncthreads();
            u64 acc[2][8];
#pragma unroll
            for (int g2=0;g2<2;g2++)
#pragma unroll
                for (int bp=0;bp<8;bp++) acc[g2][bp]=0ull;
#pragma unroll
            for (int j = 0; j < 48; j++){
                int k = lane + 32*j;
                const float* row = tb + (size_t)k*XSTRIDE;
                u64 xp[8];
#pragma unroll
                for (int bp = 0; bp < 8; bp++) xp[bp] = *(const u64*)(row + 2*bp);
                F2 p0; p0.f.x = wl0[0][j]; p0.f.y = wl0[0][j];
                F2 p1; p1.f.x = wl0[1][j]; p1.f.y = wl0[1][j];
#pragma unroll
                for (int bp = 0; bp < 8; bp++){
                    fma2(acc[0][bp], p0.u, xp[bp]);
                    fma2(acc[1][bp], p1.u, xp[bp]);
                }
            }
            u64 mine = 0;
#pragma unroll
            for (int g2 = 0; g2 < 2; g2++)
#pragma unroll
                for (int bp = 0; bp < 8; bp++){
                    u64 s = wsum2(acc[g2][bp]);
                    if (lane == g2*8+bp) mine = s;
                }
            if (lane < 16){
                int gate = gp*2 + (lane >> 3);
                *(u64*)(sm + 16544 + (cl*4 + gate)*16 + 2*(lane & 7)) = mine;
            }
            __syncthreads();
            if (tid < 64){
                int ccl = tid >> 4, b = tid & 15;
                const float* gs = sm + 16544 + (ccl*4)*16;
                float gi = gs[0*16+b] + sm[16384 + ccl*4+0];
                float gf = gs[1*16+b] + sm[16384 + ccl*4+1];
                float gg = gs[2*16+b] + sm[16384 + ccl*4+2];
                float go = gs[3*16+b] + sm[16384 + ccl*4+3];
                float cprev = sm[16416 + ccl*16 + b];
                float cc = sigf(gf)*cprev + sigf(gi)*tanh_fast(gg);
                sm[16416 + ccl*16 + b] = cc;
                g_h0[np][(size_t)b*512 + bx*4 + ccl] = sigf(go)*tanh_fast(cc);
            }
        }
        gridbar(ep, NB);

        // ---- phase E: LSTM layer1 from smem weights ----
        if (lstmBlk){
            stageT(tb,   0, (const float4*)g_h0[np], 128, tid);
            stageT(tb, 512, (const float4*)g_h1[p],  128, tid);
            __syncthreads();
            u64 acc[2][8];
#pragma unroll
            for (int g2=0;g2<2;g2++)
#pragma unroll
                for (int bp=0;bp<8;bp++) acc[g2][bp]=0ull;
            const float* wbase0 = sm + (w*2+0)*1024;
            const float* wbase1 = sm + (w*2+1)*1024;
#pragma unroll
            for (int j = 0; j < 32; j++){
                int k = lane + 32*j;
                const float* row = tb + (size_t)k*XSTRIDE;
                u64 xp[8];
#pragma unroll
                for (int bp = 0; bp < 8; bp++) xp[bp] = *(const u64*)(row + 2*bp);
                float w0 = wbase0[k], w1 = wbase1[k];
                F2 p0; p0.f.x = w0; p0.f.y = w0;
                F2 p1; p1.f.x = w1; p1.f.y = w1;
#pragma unroll
                for (int bp = 0; bp < 8; bp++){
                    fma2(acc[0][bp], p0.u, xp[bp]);
                    fma2(acc[1][bp], p1.u, xp[bp]);
                }
            }
            u64 mine = 0;
#pragma unroll
            for (int g2 = 0; g2 < 2; g2++)
#pragma unroll
                for (int bp = 0; bp < 8; bp++){
                    u64 s = wsum2(acc[g2][bp]);
                    if (lane == g2*8+bp) mine = s;
                }
            if (lane < 16){
                int gate = gp*2 + (lane >> 3);
                *(u64*)(sm + 16544 + (cl*4 + gate)*16 + 2*(lane & 7)) = mine;
            }
            __syncthreads();
            if (tid < 64){
                int ccl = tid >> 4, b = tid & 15;
                const float* gs = sm + 16544 + (ccl*4)*16;
                float gi = gs[0*16+b] + sm[16400 + ccl*4+0];
                float gf = gs[1*16+b] + sm[16400 + ccl*4+1];
                float gg = gs[2*16+b] + sm[16400 + ccl*4+2];
                float go = gs[3*16+b] + sm[16400 + ccl*4+3];
                float cprev = sm[16480 + ccl*16 + b];
                float cc = sigf(gf)*cprev + sigf(gi)*tanh_fast(gg);
                sm[16480 + ccl*16 + b] = cc;
                g_h1[np][(size_t)b*512 + bx*4 + ccl] = sigf(go)*tanh_fast(cc);
            }
        }
        gridbar(ep, NB);
    }

    // ---- final logits (t-1 = 255; h1 parity 0) ----
    if (!lstmBlk){
        float4* hs4 = (float4*)tb;
        const float4* hsrc = (const float4*)g_h1[0];
        for (int i = tid; i < 2048; i += 256) hs4[i] = __ldcg(hsrc + i);
        __syncthreads();
#pragma unroll
        for (int jj = 0; jj < 4; jj++){
            int row = wr + 160*jj;
            if (row < 512 || row >= 544) continue;
            u64 acc2[16];
#pragma unroll
            for (int b=0;b<16;b++) acc2[b]=0ull;
#pragma unroll
            for (int i = 0; i < 4; i++){
#pragma unroll
                for (int b = 0; b < 16; b++){
                    F4 X; X.v = hs4[b*128 + lane + 32*i];
                    fma2(acc2[b], wqr[jj][2*i],   X.u[0]);
                    fma2(acc2[b], wqr[jj][2*i+1], X.u[1]);
                }
            }
#pragma unroll
            for (int b = 0; b < 16; b++){
                F2 z; z.u = acc2[b];
                float s = wsum(z.f.x + z.f.y);
                if (lane == b) out[((size_t)b*TT + (TT-1))*VV + (row-512)] = s + wbr[jj];
            }
        }
    }

    if (bx == 0 && tid == 0) g_epoch = ep;
}

// =====================================================================
// FALLBACK: streaming-weights persistent kernel (any co-resident grid)
// =====================================================================
template<int K>
__device__ __forceinline__ void accum_half(u64 acc[4][8], const float* __restrict__ W,
                                           int row, const float4* __restrict__ xb, int lane){
    constexpr int K4 = K/4;
    const float4* w0 = (const float4*)(W + (size_t)row*K);
    const float4* w1 = (const float4*)(W + (size_t)(row+512)*K);
    const float4* w2 = (const float4*)(W + (size_t)(row+1024)*K);
    const float4* w3 = (const float4*)(W + (size_t)(row+1536)*K);
#pragma unroll
    for (int g = 0; g < K4/128; g++){
        F4 Wb[4][4];
#pragma unroll
        for (int it = 0; it < 4; it++){
            int c = lane + 32*(g*4+it);
            Wb[it][0].v = __ldcg(w0 + c);
            Wb[it][1].v = __ldcg(w1 + c);
            Wb[it][2].v = __ldcg(w2 + c);
            Wb[it][3].v = __ldcg(w3 + c);
        }
#pragma unroll
        for (int it = 0; it < 4; it++){
            int c = lane + 32*(g*4+it);
#pragma unroll
            for (int b = 0; b < 8; b++){
                F4 X; X.v = xb[b*K4 + c];
                fma2(acc[0][b], Wb[it][0].u[0], X.u[0]); fma2(acc[0][b], Wb[it][0].u[1], X.u[1]);
                fma2(acc[1][b], Wb[it][1].u[0], X.u[0]); fma2(acc[1][b], Wb[it][1].u[1], X.u[1]);
                fma2(acc[2][b], Wb[it][2].u[0], X.u[0]); fma2(acc[2][b], Wb[it][2].u[1], X.u[1]);
                fma2(acc[3][b], Wb[it][3].u[0], X.u[0]); fma2(acc[3][b], Wb[it][3].u[1], X.u[1]);
            }
        }
    }
}
__device__ __forceinline__ void finish_half(u64 acc[4][8], int cell, int bh,
        const float* __restrict__ bih, const float* __restrict__ bhh,
        const float* __restrict__ cprev, float* __restrict__ hout, float* __restrict__ cout_,
        int lane){
    float keep[4] = {0.f,0.f,0.f,0.f};
#pragma unroll
    for (int b=0;b<8;b++){
#pragma unroll
        for (int g=0; g<4; g++){
            F2 z; z.u = acc[g][b];
            float s = wsum(z.f.x + z.f.y);
            if (lane == b) keep[g] = s;
        }
    }
    if (lane < 8){
        int b = bh*8 + lane, idx = b*HH + cell;
        float gi = keep[0] + bih[cell       ] + bhh[cell       ];
        float gf = keep[1] + bih[cell +  512] + bhh[cell +  512];
        float gg = keep[2] + bih[cell + 1024] + bhh[cell + 1024];
        float go = keep[3] + bih[cell + 1536] + bhh[cell + 1536];
        float cc = sigf(gf)*cprev[idx] + sigf(gi)*tanh_fast(gg);
        cout_[idx] = cc;
        hout [idx] = sigf(go)*tanh_fast(cc);
    }
}

__global__ __launch_bounds__(256, 1)
void decoder_stream(const float* __restrict__ enc, const float* __restrict__ h0in,
                    const float* __restrict__ c0in,
                    const float* __restrict__ Wq, const float* __restrict__ bq,
                    const float* __restrict__ Wk, const float* __restrict__ bk,
                    const float* __restrict__ v,
                    const float* __restrict__ Wih0, const float* __restrict__ bih0,
                    const float* __restrict__ Whh0, const float* __restrict__ bhh0,
                    const float* __restrict__ Wih1, const float* __restrict__ bih1,
                    const float* __restrict__ Whh1, const float* __restrict__ bhh1,
                    const float* __restrict__ Wout, const float* __restrict__ bout,
                    float* __restrict__ out)
{
    extern __shared__ float sm[];
    const int tid = threadIdx.x, bx = blockIdx.x, NB = gridDim.x;
    const int lane = tid & 31, w = tid >> 5;
    const int NW = NB * 8;
    const int wid0 = w*NB + bx;
    unsigned ep = g_epoch;

    for (int i = bx*256 + tid; i < NBATCH*HH; i += NB*256){
        g_h0[0][i] = h0in[i];
        g_h1[0][i] = h0in[NBATCH*HH + i];
        g_c0[0][i] = c0in[i];
        g_c1[0][i] = c0in[NBATCH*HH + i];
    }
    kproj_phase(enc, Wk, bk, g_Kproj, sm, NB, bx, tid);
    gridbar(ep, NB);

    for (int t = 0; t < TT; t++){
        const int p = t & 1, np = p ^ 1;
        {
            float4* hs4 = (float4*)sm;
            const float4* hsrc = (const float4*)g_h1[p];
            for (int i = tid; i < 2048; i += 256) hs4[i] = __ldcg(hsrc + i);
            __syncthreads();
            for (int task = wid0; task < 544; task += NW){
                if (task < 512)
                    dotrow16(Wq + (size_t)task*HH, hs4, bq[task], g_q + task, HH, lane);
                else if (t > 0){
                    int r = task - 512;
                    dotrow16(Wout + (size_t)r*HH, hs4, bout[r], out + (size_t)(t-1)*VV + r, TT*VV, lane);
                }
            }
        }
        gridbar(ep, NB);
        {
            float4* qs4 = (float4*)sm;
            float*  vs  = sm + NBATCH*HH;
            const float4* qsrc = (const float4*)g_q;
            for (int i = tid; i < 2048; i += 256) qs4[i] = __ldcg(qsrc + i);
            for (int i = tid; i < HH;  i += 256) vs[i] = v[i];
            __syncthreads();
            const float4* vs4 = (const float4*)vs;
            for (int pr = wid0; pr < 2048; pr += NW){
                int b = pr >> 7;
                const float4* Ka = (const float4*)(g_Kproj + ((size_t)pr*2)*HH);
                const float4* Kb = Ka + 128;
                float4 ka[4], kb[4];
#pragma unroll
                for (int i = 0; i < 4; i++){ ka[i] = __ldcg(Ka + lane + 32*i); kb[i] = __ldcg(Kb + lane + 32*i); }
                float a0 = 0.f, a1 = 0.f;
#pragma unroll
                for (int i = 0; i < 4; i++){
                    int c = lane + 32*i;
                    float4 q4 = qs4[b*128 + c];
                    float4 v4 = vs4[c];
                    a0 += v4.x * tanh_fast(q4.x + ka[i].x);
                    a0 += v4.y * tanh_fast(q4.y + ka[i].y);
                    a0 += v4.z * tanh_fast(q4.z + ka[i].z);
                    a0 += v4.w * tanh_fast(q4.w + ka[i].w);
                    a1 += v4.x * tanh_fast(q4.x + kb[i].x);
                    a1 += v4.y * tanh_fast(q4.y + kb[i].y);
                    a1 += v4.z * tanh_fast(q4.z + kb[i].z);
                    a1 += v4.w * tanh_fast(q4.w + kb[i].w);
                }
                a0 = wsum(a0); a1 = wsum(a1);
                if (lane == 0){ g_scores[2*pr] = a0; g_scores[2*pr+1] = a1; }
            }
        }
        gridbar(ep, NB);
        {
            float* ws  = sm;
            float* red = sm + 256;
            float* sP  = sm + 272;
            for (int task = bx; task < 128; task += NB){
                int b = task >> 3, hc = (task & 7) * 64;
                float s = g_scores[b*TT + tid];
                float m = wmax(s);
                if (lane == 0) red[w] = m;
                __syncthreads();
                float mx = red[0];
#pragma unroll
                for (int j = 1; j < 8; j++) mx = fmaxf(mx, red[j]);
                float e = __expf(s - mx);
                ws[tid] = e;
                float su = wsum(e);
                if (lane == 0) red[w] = su;
                __syncthreads();
                float tot = red[0];
#pragma unroll
                for (int j = 1; j < 8; j++) tot += red[j];
                float rz = 1.f / tot;
                int h = hc + (tid & 63), stripe = tid >> 6;
                const float* ep_ = enc + ((size_t)(b*TT) + stripe*64)*HH + h;
                float acc = 0.f;
#pragma unroll 8
                for (int tt = 0; tt < 64; tt++) acc += ws[stripe*64 + tt] * __ldcg(ep_ + (size_t)tt*HH);
                sP[tid] = acc; __syncthreads();
                if (tid < 64)
                    g_ctx[b*HH + hc + tid] = (sP[tid] + sP[tid+64] + sP[tid+128] + sP[tid+192]) * rz;
                __syncthreads();
            }
        }
        gridbar(ep, NB);
        {
            float4* xs4 = (float4*)sm;
            float4* hs4 = (float4*)(sm + NBATCH*1024);
            const float4* enc4 = (const float4*)enc;
            const float4* ctx4 = (const float4*)g_ctx;
            for (int i = tid; i < 4096; i += 256){
                int b = i >> 8, r = i & 255;
                xs4[i] = (r < 128) ? __ldcg(enc4 + (size_t)(b*TT + t)*128 + r) : ctx4[b*128 + (r - 128)];
            }
            const float4* hsrc = (const float4*)g_h0[p];
            for (int i = tid; i < 2048; i += 256) hs4[i] = __ldcg(hsrc + i);
            __syncthreads();
            for (int task = wid0; task < 1024; task += NW){
                int cell = task >> 1, bh = task & 1;
                u64 acc[4][8];
#pragma unroll
                for (int g=0; g<4; g++)
#pragma unroll
                    for (int b=0; b<8; b++) acc[g][b] = 0ull;
                accum_half<1024>(acc, Wih0, cell, xs4 + bh*8*256, lane);
                accum_half<512 >(acc, Whh0, cell, hs4 + bh*8*128, lane);
                finish_half(acc, cell, bh, bih0, bhh0, g_c0[p], g_h0[np], g_c0[np], lane);
            }
        }
        gridbar(ep, NB);
        {
            float4* xs4 = (float4*)sm;
            float4* hs4 = (float4*)(sm + NBATCH*HH);
            const float4* xsrc = (const float4*)g_h0[np];
            const float4* hsrc = (const float4*)g_h1[p];
            for (int i = tid; i < 2048; i += 256){ xs4[i] = __ldcg(xsrc + i); hs4[i] = __ldcg(hsrc + i); }
            __syncthreads();
            for (int task = wid0; task < 1024; task += NW){
                int cell = task >> 1, bh = task & 1;
                u64 acc[4][8];
#pragma unroll
                for (int g=0; g<4; g++)
#pragma unroll
                    for (int b=0; b<8; b++) acc[g][b] = 0ull;
                accum_half<512>(acc, Wih1, cell, xs4 + bh*8*128, lane);
                accum_half<512>(acc, Whh1, cell, hs4 + bh*8*128, lane);
                finish_half(acc, cell, bh, bih1, bhh1, g_c1[p], g_h1[np], g_c1[np], lane);
            }
        }
        gridbar(ep, NB);
    }
    {
        float4* hs4 = (float4*)sm;
        const float4* hsrc = (const float4*)g_h1[0];
        for (int i = tid; i < 2048; i += 256) hs4[i] = __ldcg(hsrc + i);
        __syncthreads();
        for (int task = wid0; task < 544; task += NW){
            if (task >= 512){
                int r = task - 512;
                dotrow16(Wout + (size_t)r*HH, hs4, bout[r], out + (size_t)(TT-1)*VV + r, TT*VV, lane);
            }
        }
    }
    if (bx == 0 && tid == 0) g_epoch = ep;
}

// ---------------- launch ----------------
extern "C" void kernel_launch(void* const* d_in, const int* in_sizes, int n_in,
                              void* d_out, int out_size){
    const float* enc   = (const float*)d_in[0];
    const float* h0in  = (const float*)d_in[1];
    const float* c0in  = (const float*)d_in[2];
    const float* Wq    = (const float*)d_in[4];
    const float* bq    = (const float*)d_in[5];
    const float* Wk    = (const float*)d_in[6];
    const float* bk    = (const float*)d_in[7];
    const float* v     = (const float*)d_in[8];
    // d_in[9] = vb (shift-invariant under softmax; omitted)
    const float* Wih0  = (const float*)d_in[10];
    const float* bih0  = (const float*)d_in[11];
    const float* Whh0  = (const float*)d_in[12];
    const float* bhh0  = (const float*)d_in[13];
    const float* Wih1  = (const float*)d_in[14];
    const float* bih1  = (const float*)d_in[15];
    const float* Whh1  = (const float*)d_in[16];
    const float* bhh1  = (const float*)d_in[17];
    const float* Wout  = (const float*)d_in[18];
    const float* bout  = (const float*)d_in[19];
    float* out = (float*)d_out;

    int dev = 0; cudaGetDevice(&dev);
    int nsm = 0; cudaDeviceGetAttribute(&nsm, cudaDevAttrMultiProcessorCount, dev);

    cudaFuncSetAttribute(decoder_reg, cudaFuncAttributeMaxDynamicSharedMemorySize, SMEM_REG);
    int maxbR = 0;
    cudaOccupancyMaxActiveBlocksPerMultiprocessor(&maxbR, decoder_reg, 256, SMEM_REG);

    if (nsm >= 148 && maxbR >= 1){
        decoder_reg<<<148, 256, SMEM_REG>>>(enc, h0in, c0in, Wq, bq, Wk, bk, v,
                                            Wih0, bih0, Whh0, bhh0,
                                            Wih1, bih1, Whh1, bhh1, Wout, bout, out);
    } else {
        const int SMEM = (NBATCH*1024 + NBATCH*512) * 4;
        cudaFuncSetAttribute(decoder_stream, cudaFuncAttributeMaxDynamicSharedMemorySize, SMEM);
        int maxb = 0;
        cudaOccupancyMaxActiveBlocksPerMultiprocessor(&maxb, decoder_stream, 256, SMEM);
        if (maxb < 1) maxb = 1;
        int grid = nsm * maxb;
        if (grid < 1) grid = 1;
        if (grid > 512) grid = 512;
        decoder_stream<<<grid, 256, SMEM>>>(enc, h0in, c0in, Wq, bq, Wk, bk, v,
                                            Wih0, bih0, Whh0, bhh0,
                                            Wih1, bih1, Whh1, bhh1, Wout, bout, out);
    }
}

// round 7
// speedup vs baseline: 1.0114x; 1.0114x over previous
#include <cuda_runtime.h>
#include <cstdint>

#define TT 256
#define HH 512
#define VV 32
#define NBATCH 16

typedef unsigned long long u64;

// ---------------- device scratch (static, no allocation) ----------------
__device__ float g_Kproj[NBATCH*TT*HH];     // 8 MB
__device__ float g_q[NBATCH*HH];
__device__ float g_scores[NBATCH*TT];
__device__ float g_ctx[NBATCH*HH];
__device__ float g_h0[2][NBATCH*HH];
__device__ float g_c0[2][NBATCH*HH];
__device__ float g_h1[2][NBATCH*HH];
__device__ float g_c1[2][NBATCH*HH];

// barrier state: monotonic across launches (graph replays) -> no reset race
__device__ unsigned g_epoch;
__device__ unsigned g_arrive;
__device__ unsigned g_release;

// ---------------- helpers ----------------
union F4 { float4 v; u64 u[2]; };
union F2 { u64 u; float2 f; };

__device__ __forceinline__ void fma2(u64 &acc, u64 a, u64 b){
    asm("fma.rn.f32x2 %0, %1, %2, %0;" : "+l"(acc) : "l"(a), "l"(b));
}
__device__ __forceinline__ float wsum(float v){
#pragma unroll
    for (int o = 16; o; o >>= 1) v += __shfl_xor_sync(0xffffffffu, v, o);
    return v;
}
__device__ __forceinline__ float wmax(float v){
#pragma unroll
    for (int o = 16; o; o >>= 1) v = fmaxf(v, __shfl_xor_sync(0xffffffffu, v, o));
    return v;
}
__device__ __forceinline__ float sigf(float x){ return 1.0f/(1.0f + __expf(-x)); }

// MUFU-free tanh, |err| ~1e-5
__device__ __forceinline__ float tanh_fast(float x){
    float u = x * 2.8853900817779268f;
    u = fminf(fmaxf(u, -30.0f), 30.0f);
    float big = u + 12582912.0f;
    int e = __float_as_int(big) - 0x4B400000;
    float fn = big - 12582912.0f;
    float f = u - fn;
    float p = 1.3333558e-3f;
    p = fmaf(p, f, 9.6181291e-3f);
    p = fmaf(p, f, 5.5504109e-2f);
    p = fmaf(p, f, 2.4022651e-1f);
    p = fmaf(p, f, 6.9314718e-1f);
    p = fmaf(p, f, 1.0f);
    float t = __int_as_float(__float_as_int(p) + (e << 23));
    float num = t - 1.0f;
    float den = t + 1.0f;
    float r = __uint_as_float(0x7EF311C3u - __float_as_uint(den));
    r = r * fmaf(-den, r, 2.0f);
    r = r * fmaf(-den, r, 2.0f);
    return num * r;
}

// grid barrier WITHOUT __threadfence (no CCTL.IVALL -> L1 survives across steps).
// Correctness: ALL cross-block mutable loads in this kernel are __ldcg (L2), and
// the release/acquire pair orders them. Read-only data (weights/enc) may use L1.
__device__ __forceinline__ void gridbar(unsigned &ep, int NB){
    __syncthreads();
    ep++;
    if (threadIdx.x == 0){
        unsigned prev;
        asm volatile("atom.add.acq_rel.gpu.u32 %0, [%1], %2;"
                     : "=r"(prev) : "l"(&g_arrive), "r"(1u) : "memory");
        if (prev + 1u == ep * (unsigned)NB){
            asm volatile("st.release.gpu.u32 [%0], %1;"
                         :: "l"(&g_release), "r"(ep) : "memory");
        } else {
            unsigned r;
            do {
                __nanosleep(20);
                asm volatile("ld.acquire.gpu.u32 %0, [%1];"
                             : "=r"(r) : "l"(&g_release) : "memory");
            } while ((int)(r - ep) < 0);
        }
    }
    __syncthreads();
}

// ---------------- batch-shared GEMV row; W via plain loads (L1-cacheable) ----
__device__ __forceinline__ void dotrow16(const float* __restrict__ Wrow,
                                         const float4* __restrict__ hs4,
                                         float bias, float* dst, int dstStride, int lane){
    u64 acc2[16];
#pragma unroll
    for (int b=0;b<16;b++) acc2[b]=0ull;
    const float4* W4 = (const float4*)Wrow;
    F4 Wv[4];
#pragma unroll
    for (int i=0;i<4;i++) Wv[i].v = W4[lane + 32*i];
#pragma unroll
    for (int i=0;i<4;i++){
#pragma unroll
        for (int b=0;b<16;b++){
            F4 X; X.v = hs4[b*128 + lane + 32*i];
            fma2(acc2[b], Wv[i].u[0], X.u[0]);
            fma2(acc2[b], Wv[i].u[1], X.u[1]);
        }
    }
#pragma unroll
    for (int b=0;b<16;b++){
        F2 z; z.u = acc2[b];
        float s = z.f.x + z.f.y;
        s = wsum(s);
        if (lane==b) dst[(size_t)b*dstStride] = s + bias;
    }
}

// ---------------- LSTM gate accumulation: 4 gates x 8 batches ----
// L1C=true: plain loads (L1-resident weights, stable task->warp map).
// L1C=false: __ldcg streaming (keeps L1 for the L1C weights).
template<int K, bool L1C>
__device__ __forceinline__ void accum_half(u64 acc[4][8], const float* __restrict__ W,
                                           int row, const float4* __restrict__ xb, int lane){
    constexpr int K4 = K/4;
    const float4* w0 = (const float4*)(W + (size_t)row*K);
    const float4* w1 = (const float4*)(W + (size_t)(row+512)*K);
    const float4* w2 = (const float4*)(W + (size_t)(row+1024)*K);
    const float4* w3 = (const float4*)(W + (size_t)(row+1536)*K);
#pragma unroll
    for (int g = 0; g < K4/128; g++){
        F4 Wb[4][4];
#pragma unroll
        for (int it = 0; it < 4; it++){
            int c = lane + 32*(g*4+it);
            if (L1C){
                Wb[it][0].v = w0[c]; Wb[it][1].v = w1[c];
                Wb[it][2].v = w2[c]; Wb[it][3].v = w3[c];
            } else {
                Wb[it][0].v = __ldcg(w0 + c); Wb[it][1].v = __ldcg(w1 + c);
                Wb[it][2].v = __ldcg(w2 + c); Wb[it][3].v = __ldcg(w3 + c);
            }
        }
#pragma unroll
        for (int it = 0; it < 4; it++){
            int c = lane + 32*(g*4+it);
#pragma unroll
            for (int b = 0; b < 8; b++){
                F4 X; X.v = xb[b*K4 + c];
                fma2(acc[0][b], Wb[it][0].u[0], X.u[0]); fma2(acc[0][b], Wb[it][0].u[1], X.u[1]);
                fma2(acc[1][b], Wb[it][1].u[0], X.u[0]); fma2(acc[1][b], Wb[it][1].u[1], X.u[1]);
                fma2(acc[2][b], Wb[it][2].u[0], X.u[0]); fma2(acc[2][b], Wb[it][2].u[1], X.u[1]);
                fma2(acc[3][b], Wb[it][3].u[0], X.u[0]); fma2(acc[3][b], Wb[it][3].u[1], X.u[1]);
            }
        }
    }
}

__device__ __forceinline__ void finish_half(u64 acc[4][8], int cell, int bh,
        const float* __restrict__ bih, const float* __restrict__ bhh,
        const float* __restrict__ cprev, float* __restrict__ hout, float* __restrict__ cout_,
        int lane){
    float keep[4] = {0.f,0.f,0.f,0.f};
#pragma unroll
    for (int b=0;b<8;b++){
#pragma unroll
        for (int g=0; g<4; g++){
            F2 z; z.u = acc[g][b];
            float s = wsum(z.f.x + z.f.y);
            if (lane == b) keep[g] = s;
        }
    }
    if (lane < 8){
        int b = bh*8 + lane, idx = b*HH + cell;
        // c-state is private to this (task -> warp) mapping, which is fixed
        // across steps -> plain load reads this SM's own coherent line.
        float gi = keep[0] + bih[cell       ] + bhh[cell       ];
        float gf = keep[1] + bih[cell +  512] + bhh[cell +  512];
        float gg = keep[2] + bih[cell + 1024] + bhh[cell + 1024];
        float go = keep[3] + bih[cell + 1536] + bhh[cell + 1536];
        float cc = sigf(gf)*cprev[idx] + sigf(gi)*tanh_fast(gg);
        cout_[idx] = cc;
        hout [idx] = sigf(go)*tanh_fast(cc);
    }
}

// ---------------- Kproj = enc @ Wk^T + bk (one-time tiled GEMM) ----------------
__device__ void kproj_phase(const float* __restrict__ A, const float* __restrict__ W,
                            const float* __restrict__ bias, float* __restrict__ C,
                            float* sm, int NB, int bx, int tid){
    float* As = sm;
    float* Ws = sm + 16*65;
    int lr = tid >> 2;
    int lk = (tid & 3) << 2;
    int tx = tid & 15, ty = tid >> 4;
    for (int tile = bx; tile < 64*8; tile += NB){
        int m0 = (tile >> 3)*64, n0 = (tile & 7)*64;
        float acc[4][4];
#pragma unroll
        for (int i=0;i<4;i++)
#pragma unroll
            for (int j=0;j<4;j++) acc[i][j]=0.f;
        for (int k0 = 0; k0 < HH; k0 += 16){
            float4 a4 = *(const float4*)(A + (size_t)(m0+lr)*HH + k0 + lk);
            float4 w4 = *(const float4*)(W + (size_t)(n0+lr)*HH + k0 + lk);
            __syncthreads();
            As[(lk+0)*65+lr]=a4.x; As[(lk+1)*65+lr]=a4.y; As[(lk+2)*65+lr]=a4.z; As[(lk+3)*65+lr]=a4.w;
            Ws[(lk+0)*65+lr]=w4.x; Ws[(lk+1)*65+lr]=w4.y; Ws[(lk+2)*65+lr]=w4.z; Ws[(lk+3)*65+lr]=w4.w;
            __syncthreads();
#pragma unroll
            for (int kk=0; kk<16; kk++){
                float av[4], wv[4];
#pragma unroll
                for (int i=0;i<4;i++){ av[i]=As[kk*65 + ty*4+i]; wv[i]=Ws[kk*65 + tx*4+i]; }
#pragma unroll
                for (int i=0;i<4;i++)
#pragma unroll
                    for (int j=0;j<4;j++) acc[i][j] += av[i]*wv[j];
            }
        }
#pragma unroll
        for (int i=0;i<4;i++){
            int m = m0 + ty*4 + i;
#pragma unroll
            for (int j=0;j<4;j++){
                int n = n0 + tx*4 + j;
                C[(size_t)m*HH + n] = acc[i][j] + bias[n];
            }
        }
        __syncthreads();
    }
}

// ---------------- the persistent kernel ----------------
__global__ __launch_bounds__(256, 1)
void decoder_persistent(const float* __restrict__ enc, const float* __restrict__ h0in,
                        const float* __restrict__ c0in,
                        const float* __restrict__ Wq, const float* __restrict__ bq,
                        const float* __restrict__ Wk, const float* __restrict__ bk,
                        const float* __restrict__ v,
                        const float* __restrict__ Wih0, const float* __restrict__ bih0,
                        const float* __restrict__ Whh0, const float* __restrict__ bhh0,
                        const float* __restrict__ Wih1, const float* __restrict__ bih1,
                        const float* __restrict__ Whh1, const float* __restrict__ bhh1,
                        const float* __restrict__ Wout, const float* __restrict__ bout,
                        float* __restrict__ out)
{
    extern __shared__ float sm[];
    const int tid = threadIdx.x, bx = blockIdx.x, NB = gridDim.x;
    const int lane = tid & 31, w = tid >> 5;
    const int NW = NB * 8;
    const int wid0 = w*NB + bx;       // block-strided id (A, B phases: balance)
    const int bxw  = bx*8 + w;        // block-major id (D, E: L1 weight locality,
                                      //   both batch-halves of a cell on one SM)
    unsigned ep = g_epoch;

    // ---- init + Kproj ----
    for (int i = bx*256 + tid; i < NBATCH*HH; i += NB*256){
        g_h0[0][i] = h0in[i];
        g_h1[0][i] = h0in[NBATCH*HH + i];
        g_c0[0][i] = c0in[i];
        g_c1[0][i] = c0in[NBATCH*HH + i];
    }
    kproj_phase(enc, Wk, bk, g_Kproj, sm, NB, bx, tid);
    gridbar(ep, NB);

    for (int t = 0; t < TT; t++){
        const int p = t & 1, np = p ^ 1;

        // ---- phase A: q = h1@Wq^T + bq ; logits[t-1] = h1@Wout^T + bout ----
        {
            float4* hs4 = (float4*)sm;
            const float4* hsrc = (const float4*)g_h1[p];
            for (int i = tid; i < 2048; i += 256) hs4[i] = __ldcg(hsrc + i);
            __syncthreads();
            for (int task = wid0; task < 544; task += NW){
                if (task < 512)
                    dotrow16(Wq + (size_t)task*HH, hs4, bq[task], g_q + task, HH, lane);
                else if (t > 0){
                    int r = task - 512;
                    dotrow16(Wout + (size_t)r*HH, hs4, bout[r],
                             out + (size_t)(t-1)*VV + r, TT*VV, lane);
                }
            }
        }
        gridbar(ep, NB);

        // ---- phase B: scores[b,tau] = sum_h v[h]*tanh(q[b,h]+Kproj[b,tau,h]) ----
        {
            float4* qs4 = (float4*)sm;
            float*  vs  = sm + NBATCH*HH;
            const float4* qsrc = (const float4*)g_q;
            for (int i = tid; i < 2048; i += 256) qs4[i] = __ldcg(qsrc + i);
            for (int i = tid; i < HH;  i += 256) vs[i] = v[i];
            __syncthreads();
            const float4* vs4 = (const float4*)vs;
            for (int pr = wid0; pr < 2048; pr += NW){
                int b = pr >> 7;
                const float4* Ka = (const float4*)(g_Kproj + ((size_t)pr*2)*HH);
                const float4* Kb = Ka + 128;
                float4 ka[4], kb[4];
#pragma unroll
                for (int i = 0; i < 4; i++){
                    ka[i] = __ldcg(Ka + lane + 32*i);
                    kb[i] = __ldcg(Kb + lane + 32*i);
                }
                float a0 = 0.f, a1 = 0.f;
#pragma unroll
                for (int i = 0; i < 4; i++){
                    int c = lane + 32*i;
                    float4 q4 = qs4[b*128 + c];
                    float4 v4 = vs4[c];
                    a0 += v4.x * tanh_fast(q4.x + ka[i].x);
                    a0 += v4.y * tanh_fast(q4.y + ka[i].y);
                    a0 += v4.z * tanh_fast(q4.z + ka[i].z);
                    a0 += v4.w * tanh_fast(q4.w + ka[i].w);
                    a1 += v4.x * tanh_fast(q4.x + kb[i].x);
                    a1 += v4.y * tanh_fast(q4.y + kb[i].y);
                    a1 += v4.z * tanh_fast(q4.z + kb[i].z);
                    a1 += v4.w * tanh_fast(q4.w + kb[i].w);
                }
                a0 = wsum(a0); a1 = wsum(a1);
                if (lane == 0){ g_scores[2*pr] = a0; g_scores[2*pr+1] = a1; }
            }
        }
        gridbar(ep, NB);

        // ---- phase C: softmax over T + ctx = w @ enc (128 tasks) ----
        {
            float* ws  = sm;
            float* red = sm + 256;
            float* sP  = sm + 272;
            for (int task = bx; task < 128; task += NB){
                int b = task >> 3, hc = (task & 7) * 64;
                float s = __ldcg(&g_scores[b*TT + tid]);
                float m = wmax(s);
                if (lane == 0) red[w] = m;
                __syncthreads();
                float mx = red[0];
#pragma unroll
                for (int j = 1; j < 8; j++) mx = fmaxf(mx, red[j]);
                float e = __expf(s - mx);
                ws[tid] = e;
                float su = wsum(e);
                if (lane == 0) red[w] = su;
                __syncthreads();
                float tot = red[0];
#pragma unroll
                for (int j = 1; j < 8; j++) tot += red[j];
                float rz = 1.f / tot;
                int h = hc + (tid & 63), stripe = tid >> 6;
                const float* ep_ = enc + ((size_t)(b*TT) + stripe*64)*HH + h;
                float acc = 0.f;
#pragma unroll 8
                for (int tt = 0; tt < 64; tt++) acc += ws[stripe*64 + tt] * __ldcg(ep_ + (size_t)tt*HH);
                sP[tid] = acc; __syncthreads();
                if (tid < 64)
                    g_ctx[b*HH + hc + tid] = (sP[tid] + sP[tid+64] + sP[tid+128] + sP[tid+192]) * rz;
                __syncthreads();
            }
        }
        gridbar(ep, NB);

        // ---- phase D: LSTM layer 0, K=1024; block-major tasks, L1-resident W ----
        {
            float4* xs4 = (float4*)sm;                    // [16][256] float4 = 64KB
            float4* hs4 = (float4*)(sm + NBATCH*1024);    // [16][128] float4 = 32KB
            const float4* enc4 = (const float4*)enc;
            const float4* ctx4 = (const float4*)g_ctx;
            for (int i = tid; i < 4096; i += 256){
                int b = i >> 8, r = i & 255;
                xs4[i] = (r < 128) ? __ldcg(enc4 + (size_t)(b*TT + t)*128 + r)
                                   : __ldcg(ctx4 + b*128 + (r - 128));
            }
            const float4* hsrc = (const float4*)g_h0[p];
            for (int i = tid; i < 2048; i += 256) hs4[i] = __ldcg(hsrc + i);
            __syncthreads();
            for (int task = bxw; task < 1024; task += NW){
                int cell = task >> 1, bh = task & 1;
                u64 acc[4][8];
#pragma unroll
                for (int g=0; g<4; g++)
#pragma unroll
                    for (int b=0; b<8; b++) acc[g][b] = 0ull;
                accum_half<1024,true>(acc, Wih0, cell, xs4 + bh*8*256, lane);
                accum_half<512 ,true>(acc, Whh0, cell, hs4 + bh*8*128, lane);
                finish_half(acc, cell, bh, bih0, bhh0, g_c0[p], g_h0[np], g_c0[np], lane);
            }
        }
        gridbar(ep, NB);

        // ---- phase E: LSTM layer 1, K=512; block-major tasks, streamed W ----
        {
            float4* xs4 = (float4*)sm;
            float4* hs4 = (float4*)(sm + NBATCH*HH);
            const float4* xsrc = (const float4*)g_h0[np];
            const float4* hsrc = (const float4*)g_h1[p];
            for (int i = tid; i < 2048; i += 256){
                xs4[i] = __ldcg(xsrc + i);
                hs4[i] = __ldcg(hsrc + i);
            }
            __syncthreads();
            for (int task = bxw; task < 1024; task += NW){
                int cell = task >> 1, bh = task & 1;
                u64 acc[4][8];
#pragma unroll
                for (int g=0; g<4; g++)
#pragma unroll
                    for (int b=0; b<8; b++) acc[g][b] = 0ull;
                accum_half<512,false>(acc, Wih1, cell, xs4 + bh*8*128, lane);
                accum_half<512,false>(acc, Whh1, cell, hs4 + bh*8*128, lane);
                finish_half(acc, cell, bh, bih1, bhh1, g_c1[p], g_h1[np], g_c1[np], lane);
            }
        }
        gridbar(ep, NB);
    }

    // ---- final logits for t = 255 (state parity 0 after step 255) ----
    {
        float4* hs4 = (float4*)sm;
        const float4* hsrc = (const float4*)g_h1[0];
        for (int i = tid; i < 2048; i += 256) hs4[i] = __ldcg(hsrc + i);
        __syncthreads();
        for (int task = wid0; task < 544; task += NW){
            if (task >= 512){
                int r = task - 512;
                dotrow16(Wout + (size_t)r*HH, hs4, bout[r],
                         out + (size_t)(TT-1)*VV + r, TT*VV, lane);
            }
        }
    }

    if (bx == 0 && tid == 0) g_epoch = ep;   // persist epoch base for next launch
}

// ---------------- launch ----------------
extern "C" void kernel_launch(void* const* d_in, const int* in_sizes, int n_in,
                              void* d_out, int out_size){
    const float* enc   = (const float*)d_in[0];
    const float* h0in  = (const float*)d_in[1];
    const float* c0in  = (const float*)d_in[2];
    // d_in[3] = audio_lengths (unused by the reference math)
    const float* Wq    = (const float*)d_in[4];
    const float* bq    = (const float*)d_in[5];
    const float* Wk    = (const float*)d_in[6];
    const float* bk    = (const float*)d_in[7];
    const float* v     = (const float*)d_in[8];
    // d_in[9] = vb (shift-invariant under softmax; omitted)
    const float* Wih0  = (const float*)d_in[10];
    const float* bih0  = (const float*)d_in[11];
    const float* Whh0  = (const float*)d_in[12];
    const float* bhh0  = (const float*)d_in[13];
    const float* Wih1  = (const float*)d_in[14];
    const float* bih1  = (const float*)d_in[15];
    const float* Whh1  = (const float*)d_in[16];
    const float* Whh1b = nullptr; (void)Whh1b;
    const float* bhh1  = (const float*)d_in[17];
    const float* Wout  = (const float*)d_in[18];
    const float* bout  = (const float*)d_in[19];
    float* out = (float*)d_out;

    const int SMEM = (NBATCH*1024 + NBATCH*512) * 4;   // 98304 bytes (phase D peak)
    cudaFuncSetAttribute(decoder_persistent, cudaFuncAttributeMaxDynamicSharedMemorySize, SMEM);

    // grid = exactly the number of co-resident blocks (deadlock-proof)
    int dev = 0; cudaGetDevice(&dev);
    int nsm = 0; cudaDeviceGetAttribute(&nsm, cudaDevAttrMultiProcessorCount, dev);
    int maxb = 0;
    cudaOccupancyMaxActiveBlocksPerMultiprocessor(&maxb, decoder_persistent, 256, SMEM);
    if (maxb < 1) maxb = 1;
    int grid = nsm * maxb;
    if (grid < 1) grid = 1;
    if (grid > 512) grid = 512;

    decoder_persistent<<<grid, 256, SMEM>>>(enc, h0in, c0in, Wq, bq, Wk, bk, v,
                                            Wih0, bih0, Whh0, bhh0,
                                            Wih1, bih1, Whh1, bhh1,
                                            Wout, bout, out);
}

// round 8
// speedup vs baseline: 1.5073x; 1.4903x over previous
#include <cuda_runtime.h>
#include <cstdint>

#define TT 256
#define HH 512
#define VV 32
#define NBATCH 16
#define THREADS 512

typedef unsigned long long u64;

// ---------------- device scratch (static, no allocation) ----------------
__device__ float g_Kproj[NBATCH*TT*HH];     // 8 MB
__device__ float g_q[NBATCH*HH];
__device__ float g_scores[NBATCH*TT];
__device__ float g_ctx[NBATCH*HH];
__device__ float g_h0[2][NBATCH*HH];
__device__ float g_c0[2][NBATCH*HH];
__device__ float g_h1[2][NBATCH*HH];
__device__ float g_c1[2][NBATCH*HH];

// barrier state: monotonic across launches (graph replays) -> no reset race
__device__ unsigned g_epoch;
__device__ unsigned g_arrive;
__device__ unsigned g_release;

// ---------------- helpers ----------------
union F4 { float4 v; u64 u[2]; };
union F2 { u64 u; float2 f; };

__device__ __forceinline__ void fma2(u64 &acc, u64 a, u64 b){
    asm("fma.rn.f32x2 %0, %1, %2, %0;" : "+l"(acc) : "l"(a), "l"(b));
}
__device__ __forceinline__ float wsum(float v){
#pragma unroll
    for (int o = 16; o; o >>= 1) v += __shfl_xor_sync(0xffffffffu, v, o);
    return v;
}
__device__ __forceinline__ float wmax(float v){
#pragma unroll
    for (int o = 16; o; o >>= 1) v = fmaxf(v, __shfl_xor_sync(0xffffffffu, v, o));
    return v;
}
__device__ __forceinline__ float sigf(float x){ return 1.0f/(1.0f + __expf(-x)); }

// MUFU-free tanh, |err| ~1e-5
__device__ __forceinline__ float tanh_fast(float x){
    float u = x * 2.8853900817779268f;
    u = fminf(fmaxf(u, -30.0f), 30.0f);
    float big = u + 12582912.0f;
    int e = __float_as_int(big) - 0x4B400000;
    float fn = big - 12582912.0f;
    float f = u - fn;
    float p = 1.3333558e-3f;
    p = fmaf(p, f, 9.6181291e-3f);
    p = fmaf(p, f, 5.5504109e-2f);
    p = fmaf(p, f, 2.4022651e-1f);
    p = fmaf(p, f, 6.9314718e-1f);
    p = fmaf(p, f, 1.0f);
    float t = __int_as_float(__float_as_int(p) + (e << 23));
    float num = t - 1.0f;
    float den = t + 1.0f;
    float r = __uint_as_float(0x7EF311C3u - __float_as_uint(den));
    r = r * fmaf(-den, r, 2.0f);
    r = r * fmaf(-den, r, 2.0f);
    return num * r;
}

// grid barrier: atomic arrive + single release flag (R5-proven semantics)
__device__ __forceinline__ void gridbar(unsigned &ep, int NB){
    __syncthreads();
    ep++;
    if (threadIdx.x == 0){
        __threadfence();
        unsigned prev = atomicAdd(&g_arrive, 1u);
        if (prev + 1u == ep * (unsigned)NB){
            __threadfence();
            *(volatile unsigned*)&g_release = ep;
        } else {
            while (*(volatile unsigned*)&g_release < ep) { }
        }
        __threadfence();
    }
    __syncthreads();
}

// ---------------- batch-shared GEMV row (16 batches, W prefetched) ----------
__device__ __forceinline__ void dotrow16(const float* __restrict__ Wrow,
                                         const float4* __restrict__ hs4,
                                         float bias, float* dst, int dstStride, int lane){
    u64 acc2[16];
#pragma unroll
    for (int b=0;b<16;b++) acc2[b]=0ull;
    const float4* W4 = (const float4*)Wrow;
    F4 Wv[4];
#pragma unroll
    for (int i=0;i<4;i++) Wv[i].v = __ldcg(W4 + lane + 32*i);
#pragma unroll
    for (int i=0;i<4;i++){
#pragma unroll
        for (int b=0;b<16;b++){
            F4 X; X.v = hs4[b*128 + lane + 32*i];
            fma2(acc2[b], Wv[i].u[0], X.u[0]);
            fma2(acc2[b], Wv[i].u[1], X.u[1]);
        }
    }
#pragma unroll
    for (int b=0;b<16;b++){
        F2 z; z.u = acc2[b];
        float s = z.f.x + z.f.y;
        s = wsum(s);
        if (lane==b) dst[(size_t)b*dstStride] = s + bias;
    }
}

// ---------------- LSTM gate accumulation: 4 gates x 4 batches (batch-quarter) ----
// W loads grouped 8-deep per warp; 16 warps/SM keep 128 loads in flight per SM.
template<int K>
__device__ __forceinline__ void accum_quarter(u64 acc[4][4], const float* __restrict__ W,
                                              int row, const float4* __restrict__ xb, int lane){
    constexpr int K4 = K/4;
    const float4* w0 = (const float4*)(W + (size_t)row*K);
    const float4* w1 = (const float4*)(W + (size_t)(row+512)*K);
    const float4* w2 = (const float4*)(W + (size_t)(row+1024)*K);
    const float4* w3 = (const float4*)(W + (size_t)(row+1536)*K);
#pragma unroll
    for (int g = 0; g < K4/64; g++){
        F4 Wb[2][4];
#pragma unroll
        for (int it = 0; it < 2; it++){
            int c = lane + 32*(g*2+it);
            Wb[it][0].v = __ldcg(w0 + c);
            Wb[it][1].v = __ldcg(w1 + c);
            Wb[it][2].v = __ldcg(w2 + c);
            Wb[it][3].v = __ldcg(w3 + c);
        }
#pragma unroll
        for (int it = 0; it < 2; it++){
            int c = lane + 32*(g*2+it);
#pragma unroll
            for (int b = 0; b < 4; b++){
                F4 X; X.v = xb[b*K4 + c];
                fma2(acc[0][b], Wb[it][0].u[0], X.u[0]); fma2(acc[0][b], Wb[it][0].u[1], X.u[1]);
                fma2(acc[1][b], Wb[it][1].u[0], X.u[0]); fma2(acc[1][b], Wb[it][1].u[1], X.u[1]);
                fma2(acc[2][b], Wb[it][2].u[0], X.u[0]); fma2(acc[2][b], Wb[it][2].u[1], X.u[1]);
                fma2(acc[3][b], Wb[it][3].u[0], X.u[0]); fma2(acc[3][b], Wb[it][3].u[1], X.u[1]);
            }
        }
    }
}

__device__ __forceinline__ void finish_quarter(u64 acc[4][4], int cell, int bq,
        const float* __restrict__ bih, const float* __restrict__ bhh,
        const float* __restrict__ cprev, float* __restrict__ hout, float* __restrict__ cout_,
        int lane){
    float keep[4] = {0.f,0.f,0.f,0.f};
#pragma unroll
    for (int b=0;b<4;b++){
#pragma unroll
        for (int g=0; g<4; g++){
            F2 z; z.u = acc[g][b];
            float s = wsum(z.f.x + z.f.y);
            if (lane == b) keep[g] = s;
        }
    }
    if (lane < 4){
        int b = bq*4 + lane, idx = b*HH + cell;
        float gi = keep[0] + bih[cell       ] + bhh[cell       ];
        float gf = keep[1] + bih[cell +  512] + bhh[cell +  512];
        float gg = keep[2] + bih[cell + 1024] + bhh[cell + 1024];
        float go = keep[3] + bih[cell + 1536] + bhh[cell + 1536];
        float cc = sigf(gf)*cprev[idx] + sigf(gi)*tanh_fast(gg);
        cout_[idx] = cc;
        hout [idx] = sigf(go)*tanh_fast(cc);
    }
}

// ---------------- Kproj = enc @ Wk^T + bk (one-time tiled GEMM; first 256 threads) ----
__device__ void kproj_phase(const float* __restrict__ A, const float* __restrict__ W,
                            const float* __restrict__ bias, float* __restrict__ C,
                            float* sm, int NB, int bx, int tid){
    float* As = sm;
    float* Ws = sm + 16*65;
    int lr = tid >> 2;
    int lk = (tid & 3) << 2;
    int tx = tid & 15, ty = (tid >> 4) & 15;
    const bool act = (tid < 256);
    for (int tile = bx; tile < 64*8; tile += NB){
        int m0 = (tile >> 3)*64, n0 = (tile & 7)*64;
        float acc[4][4];
#pragma unroll
        for (int i=0;i<4;i++)
#pragma unroll
            for (int j=0;j<4;j++) acc[i][j]=0.f;
        for (int k0 = 0; k0 < HH; k0 += 16){
            float4 a4 = make_float4(0,0,0,0), w4 = make_float4(0,0,0,0);
            if (act){
                a4 = *(const float4*)(A + (size_t)(m0+lr)*HH + k0 + lk);
                w4 = *(const float4*)(W + (size_t)(n0+lr)*HH + k0 + lk);
            }
            __syncthreads();
            if (act){
                As[(lk+0)*65+lr]=a4.x; As[(lk+1)*65+lr]=a4.y; As[(lk+2)*65+lr]=a4.z; As[(lk+3)*65+lr]=a4.w;
                Ws[(lk+0)*65+lr]=w4.x; Ws[(lk+1)*65+lr]=w4.y; Ws[(lk+2)*65+lr]=w4.z; Ws[(lk+3)*65+lr]=w4.w;
            }
            __syncthreads();
            if (act){
#pragma unroll
                for (int kk=0; kk<16; kk++){
                    float av[4], wv[4];
#pragma unroll
                    for (int i=0;i<4;i++){ av[i]=As[kk*65 + ty*4+i]; wv[i]=Ws[kk*65 + tx*4+i]; }
#pragma unroll
                    for (int i=0;i<4;i++)
#pragma unroll
                        for (int j=0;j<4;j++) acc[i][j] += av[i]*wv[j];
                }
            }
        }
        if (act){
#pragma unroll
            for (int i=0;i<4;i++){
                int m = m0 + ty*4 + i;
#pragma unroll
                for (int j=0;j<4;j++){
                    int n = n0 + tx*4 + j;
                    C[(size_t)m*HH + n] = acc[i][j] + bias[n];
                }
            }
        }
        __syncthreads();
    }
}

// ---------------- the persistent kernel ----------------
__global__ __launch_bounds__(THREADS, 1)
void decoder_persistent(const float* __restrict__ enc, const float* __restrict__ h0in,
                        const float* __restrict__ c0in,
                        const float* __restrict__ Wq, const float* __restrict__ bq,
                        const float* __restrict__ Wk, const float* __restrict__ bk,
                        const float* __restrict__ v,
                        const float* __restrict__ Wih0, const float* __restrict__ bih0,
                        const float* __restrict__ Whh0, const float* __restrict__ bhh0,
                        const float* __restrict__ Wih1, const float* __restrict__ bih1,
                        const float* __restrict__ Whh1, const float* __restrict__ bhh1,
                        const float* __restrict__ Wout, const float* __restrict__ bout,
                        float* __restrict__ out)
{
    extern __shared__ float sm[];
    const int tid = threadIdx.x, bx = blockIdx.x, NB = gridDim.x;
    const int lane = tid & 31, w = tid >> 5;            // 16 warps/block
    const int NW = NB * 16;
    const int wid0 = w*NB + bx;                          // block-strided warp id
    unsigned ep = g_epoch;

    // ---- init + Kproj ----
    for (int i = bx*THREADS + tid; i < NBATCH*HH; i += NB*THREADS){
        g_h0[0][i] = h0in[i];
        g_h1[0][i] = h0in[NBATCH*HH + i];
        g_c0[0][i] = c0in[i];
        g_c1[0][i] = c0in[NBATCH*HH + i];
    }
    kproj_phase(enc, Wk, bk, g_Kproj, sm, NB, bx, tid);
    gridbar(ep, NB);

    for (int t = 0; t < TT; t++){
        const int p = t & 1, np = p ^ 1;

        // ---- phase A: q = h1@Wq^T + bq ; logits[t-1] = h1@Wout^T + bout ----
        {
            float4* hs4 = (float4*)sm;
            const float4* hsrc = (const float4*)g_h1[p];
            for (int i = tid; i < 2048; i += THREADS) hs4[i] = __ldcg(hsrc + i);
            __syncthreads();
            for (int task = wid0; task < 544; task += NW){
                if (task < 512)
                    dotrow16(Wq + (size_t)task*HH, hs4, bq[task], g_q + task, HH, lane);
                else if (t > 0){
                    int r = task - 512;
                    dotrow16(Wout + (size_t)r*HH, hs4, bout[r],
                             out + (size_t)(t-1)*VV + r, TT*VV, lane);
                }
            }
        }
        gridbar(ep, NB);

        // ---- phase B: scores[b,tau] = sum_h v[h]*tanh(q[b,h]+Kproj[b,tau,h]) ----
        {
            float4* qs4 = (float4*)sm;
            float*  vs  = sm + NBATCH*HH;
            const float4* qsrc = (const float4*)g_q;
            for (int i = tid; i < 2048; i += THREADS) qs4[i] = __ldcg(qsrc + i);
            for (int i = tid; i < HH;  i += THREADS) vs[i] = v[i];
            __syncthreads();
            const float4* vs4 = (const float4*)vs;
            for (int pr = wid0; pr < 2048; pr += NW){
                int b = pr >> 7;
                const float4* Ka = (const float4*)(g_Kproj + ((size_t)pr*2)*HH);
                const float4* Kb = Ka + 128;
                float4 ka[4], kb[4];
#pragma unroll
                for (int i = 0; i < 4; i++){
                    ka[i] = __ldcg(Ka + lane + 32*i);
                    kb[i] = __ldcg(Kb + lane + 32*i);
                }
                float a0 = 0.f, a1 = 0.f;
#pragma unroll
                for (int i = 0; i < 4; i++){
                    int c = lane + 32*i;
                    float4 q4 = qs4[b*128 + c];
                    float4 v4 = vs4[c];
                    a0 += v4.x * tanh_fast(q4.x + ka[i].x);
                    a0 += v4.y * tanh_fast(q4.y + ka[i].y);
                    a0 += v4.z * tanh_fast(q4.z + ka[i].z);
                    a0 += v4.w * tanh_fast(q4.w + ka[i].w);
                    a1 += v4.x * tanh_fast(q4.x + kb[i].x);
                    a1 += v4.y * tanh_fast(q4.y + kb[i].y);
                    a1 += v4.z * tanh_fast(q4.z + kb[i].z);
                    a1 += v4.w * tanh_fast(q4.w + kb[i].w);
                }
                a0 = wsum(a0); a1 = wsum(a1);
                if (lane == 0){ g_scores[2*pr] = a0; g_scores[2*pr+1] = a1; }
            }
        }
        gridbar(ep, NB);

        // ---- phase C: softmax over T + ctx = w @ enc (128 tasks: 16b x 8 h-chunks) ----
        {
            float* ws  = sm;          // [256]
            float* red = sm + 256;    // [8]
            float* sP  = sm + 272;    // [512]
            for (int task = bx; task < 128; task += NB){
                int b = task >> 3, hc = (task & 7) * 64;
                float s = 0.f;
                if (tid < 256){
                    s = g_scores[b*TT + tid];
                    float m = wmax(s);
                    if (lane == 0) red[w] = m;
                }
                __syncthreads();
                float mx = red[0];
#pragma unroll
                for (int j = 1; j < 8; j++) mx = fmaxf(mx, red[j]);
                if (tid < 256){
                    float e = __expf(s - mx);
                    ws[tid] = e;
                    float su = wsum(e);
                    if (lane == 0) red[w] = su;
                }
                __syncthreads();
                float tot = red[0];
#pragma unroll
                for (int j = 1; j < 8; j++) tot += red[j];
                float rz = 1.f / tot;
                int h = hc + (tid & 63), stripe = tid >> 6;       // 8 stripes of 32 taus
                const float* ep_ = enc + ((size_t)(b*TT) + stripe*32)*HH + h;
                float acc = 0.f;
#pragma unroll 8
                for (int tt = 0; tt < 32; tt++) acc += ws[stripe*32 + tt] * __ldcg(ep_ + (size_t)tt*HH);
                sP[tid] = acc; __syncthreads();
                if (tid < 64){
                    float r2 = sP[tid];
#pragma unroll
                    for (int j = 1; j < 8; j++) r2 += sP[tid + 64*j];
                    g_ctx[b*HH + hc + tid] = r2 * rz;
                }
                __syncthreads();
            }
        }
        gridbar(ep, NB);

        // ---- phase D: LSTM layer 0, K=1536 total; 2048 tasks (cell, bquarter) ----
        {
            float4* xs4 = (float4*)sm;                    // [16][256] float4 = 64KB
            float4* hs4 = (float4*)(sm + NBATCH*1024);    // [16][128] float4 = 32KB
            const float4* enc4 = (const float4*)enc;
            const float4* ctx4 = (const float4*)g_ctx;
            for (int i = tid; i < 4096; i += THREADS){
                int b = i >> 8, r = i & 255;
                xs4[i] = (r < 128) ? __ldcg(enc4 + (size_t)(b*TT + t)*128 + r)
                                   : __ldcg(ctx4 + b*128 + (r - 128));
            }
            const float4* hsrc = (const float4*)g_h0[p];
            for (int i = tid; i < 2048; i += THREADS) hs4[i] = __ldcg(hsrc + i);
            __syncthreads();
            for (int task = wid0; task < 2048; task += NW){
                int cell = task >> 2, bq2 = task & 3;
                u64 acc[4][4];
#pragma unroll
                for (int g=0; g<4; g++)
#pragma unroll
                    for (int b=0; b<4; b++) acc[g][b] = 0ull;
                accum_quarter<1024>(acc, Wih0, cell, xs4 + bq2*4*256, lane);
                accum_quarter<512 >(acc, Whh0, cell, hs4 + bq2*4*128, lane);
                finish_quarter(acc, cell, bq2, bih0, bhh0, g_c0[p], g_h0[np], g_c0[np], lane);
            }
        }
        gridbar(ep, NB);

        // ---- phase E: LSTM layer 1, K=1024 total; 2048 tasks ----
        {
            float4* xs4 = (float4*)sm;                    // [16][128] float4
            float4* hs4 = (float4*)(sm + NBATCH*HH);      // [16][128] float4
            const float4* xsrc = (const float4*)g_h0[np];
            const float4* hsrc = (const float4*)g_h1[p];
            for (int i = tid; i < 2048; i += THREADS){
                xs4[i] = __ldcg(xsrc + i);
                hs4[i] = __ldcg(hsrc + i);
            }
            __syncthreads();
            for (int task = wid0; task < 2048; task += NW){
                int cell = task >> 2, bq2 = task & 3;
                u64 acc[4][4];
#pragma unroll
                for (int g=0; g<4; g++)
#pragma unroll
                    for (int b=0; b<4; b++) acc[g][b] = 0ull;
                accum_quarter<512>(acc, Wih1, cell, xs4 + bq2*4*128, lane);
                accum_quarter<512>(acc, Whh1, cell, hs4 + bq2*4*128, lane);
                finish_quarter(acc, cell, bq2, bih1, bhh1, g_c1[p], g_h1[np], g_c1[np], lane);
            }
        }
        gridbar(ep, NB);
    }

    // ---- final logits for t = 255 (state parity 0 after step 255) ----
    {
        float4* hs4 = (float4*)sm;
        const float4* hsrc = (const float4*)g_h1[0];
        for (int i = tid; i < 2048; i += THREADS) hs4[i] = __ldcg(hsrc + i);
        __syncthreads();
        for (int task = wid0; task < 544; task += NW){
            if (task >= 512){
                int r = task - 512;
                dotrow16(Wout + (size_t)r*HH, hs4, bout[r],
                         out + (size_t)(TT-1)*VV + r, TT*VV, lane);
            }
        }
    }

    if (bx == 0 && tid == 0) g_epoch = ep;   // persist epoch base for next launch
}

// ---------------- launch ----------------
extern "C" void kernel_launch(void* const* d_in, const int* in_sizes, int n_in,
                              void* d_out, int out_size){
    const float* enc   = (const float*)d_in[0];
    const float* h0in  = (const float*)d_in[1];
    const float* c0in  = (const float*)d_in[2];
    // d_in[3] = audio_lengths (unused by the reference math)
    const float* Wq    = (const float*)d_in[4];
    const float* bq    = (const float*)d_in[5];
    const float* Wk    = (const float*)d_in[6];
    const float* bk    = (const float*)d_in[7];
    const float* v     = (const float*)d_in[8];
    // d_in[9] = vb (shift-invariant under softmax; omitted)
    const float* Wih0  = (const float*)d_in[10];
    const float* bih0  = (const float*)d_in[11];
    const float* Whh0  = (const float*)d_in[12];
    const float* bhh0  = (const float*)d_in[13];
    const float* Wih1  = (const float*)d_in[14];
    const float* bih1  = (const float*)d_in[15];
    const float* Whh1  = (const float*)d_in[16];
    const float* bhh1  = (const float*)d_in[17];
    const float* Wout  = (const float*)d_in[18];
    const float* bout  = (const float*)d_in[19];
    float* out = (float*)d_out;

    const int SMEM = (NBATCH*1024 + NBATCH*512) * 4;   // 98304 bytes (phase D peak)
    cudaFuncSetAttribute(decoder_persistent, cudaFuncAttributeMaxDynamicSharedMemorySize, SMEM);

    // grid = exactly the number of co-resident blocks (deadlock-proof)
    int dev = 0; cudaGetDevice(&dev);
    int nsm = 0; cudaDeviceGetAttribute(&nsm, cudaDevAttrMultiProcessorCount, dev);
    int maxb = 0;
    cudaOccupancyMaxActiveBlocksPerMultiprocessor(&maxb, decoder_persistent, THREADS, SMEM);
    if (maxb < 1) maxb = 1;
    int grid = nsm * maxb;
    if (grid < 1) grid = 1;
    if (grid > 512) grid = 512;

    decoder_persistent<<<grid, THREADS, SMEM>>>(enc, h0in, c0in, Wq, bq, Wk, bk, v,
                                                Wih0, bih0, Whh0, bhh0,
                                                Wih1, bih1, Whh1, bhh1,
                                                Wout, bout, out);
}